// round 6
// baseline (speedup 1.0000x reference)
#include <cuda_runtime.h>

#define BATCH   1048576
#define DT      0.0166667f
#define SLOPE   0.01f
#define NN_RATIO 0.5f
#define THREADS 256

// Shared-memory layout (floats), all offsets 16B aligned where needed
#define OFF_W1 0        // 2*3*32 = 192
#define OFF_B1 192      // 2*32   = 64
#define OFF_W2 256      // 2*32*32= 2048
#define OFF_B2 2304     // 64
#define OFF_W3 2368     // 2048
#define OFF_B3 4416     // 64
#define OFF_W4 4480     // 2*32   = 64
#define OFF_B4 4544     // 2
#define SM_TOTAL 4548

__device__ __forceinline__ float leaky(float x) {
    return x >= 0.0f ? x : SLOPE * x;
}

__global__ void __launch_bounds__(THREADS) joint1dof_kernel(
    const float* __restrict__ SS, const float* __restrict__ Alphas,
    const float* __restrict__ K0s, const float* __restrict__ K1s,
    const float* __restrict__ L0s, const float* __restrict__ L1s,
    const float* __restrict__ Ms,  const float* __restrict__ I_p,
    const float* __restrict__ B_p, const float* __restrict__ K_p,
    const float* __restrict__ W1, const float* __restrict__ b1,
    const float* __restrict__ W2, const float* __restrict__ b2,
    const float* __restrict__ W3, const float* __restrict__ b3,
    const float* __restrict__ W4, const float* __restrict__ b4,
    float* __restrict__ out, int B)
{
    __shared__ __align__(16) float sm[SM_TOTAL];

    const int tid = threadIdx.x;
    // Cooperative weight load into shared
    for (int i = tid; i < 192;  i += THREADS) sm[OFF_W1 + i] = W1[i];
    for (int i = tid; i < 64;   i += THREADS) sm[OFF_B1 + i] = b1[i];
    for (int i = tid; i < 2048; i += THREADS) sm[OFF_W2 + i] = W2[i];
    for (int i = tid; i < 64;   i += THREADS) sm[OFF_B2 + i] = b2[i];
    for (int i = tid; i < 2048; i += THREADS) sm[OFF_W3 + i] = W3[i];
    for (int i = tid; i < 64;   i += THREADS) sm[OFF_B3 + i] = b3[i];
    for (int i = tid; i < 64;   i += THREADS) sm[OFF_W4 + i] = W4[i];
    for (int i = tid; i < 2;    i += THREADS) sm[OFF_B4 + i] = b4[i];
    __syncthreads();

    const int b = blockIdx.x * THREADS + tid;
    if (b >= B) return;

    const float2 ssv = ((const float2*)SS)[b];
    const float2 alv = ((const float2*)Alphas)[b];
    const float ss0 = ssv.x, ss1 = ssv.y;

    // Scalars (uniform broadcast loads)
    const float I0  = __ldg(&I_p[0]);
    const float B0p = __ldg(&B_p[0]);
    const float K0p = __ldg(&K_p[0]);

    float Ktot = 0.0f, Bsum = 0.0f;

    #pragma unroll 1
    for (int m = 0; m < 2; m++) {
        const float Msm = __ldg(&Ms[m]);
        const float k0  = __ldg(&K0s[m]);
        const float k1  = __ldg(&K1s[m]);
        const float l0  = __ldg(&L0s[m]);
        const float l1  = __ldg(&L1s[m]);

        float am = (m == 0) ? alv.x : alv.y;
        am = fminf(fmaxf(am, 0.0f), 1.0f);
        const float l  = ss0 * Msm;
        const float dl = ss1 * Msm;

        const float* W1m = &sm[OFF_W1 + m * 96];
        const float* b1m = &sm[OFF_B1 + m * 32];
        const float* W2m = &sm[OFF_W2 + m * 1024];
        const float* b2m = &sm[OFF_B2 + m * 32];
        const float* W3m = &sm[OFF_W3 + m * 1024];
        const float* b3m = &sm[OFF_B3 + m * 32];
        const float* W4m = &sm[OFF_W4 + m * 32];
        const float  b4m = sm[OFF_B4 + m];

        float h[32];
        // Layer 1: 3 -> 32
        #pragma unroll
        for (int o = 0; o < 32; o++) {
            float v = b1m[o];
            v = fmaf(l,  W1m[o],      v);
            v = fmaf(dl, W1m[32 + o], v);
            v = fmaf(am, W1m[64 + o], v);
            h[o] = leaky(v);
        }
        // Layer 2: 32 -> 32
        {
            float acc[32];
            #pragma unroll
            for (int o = 0; o < 32; o++) acc[o] = b2m[o];
            #pragma unroll
            for (int i = 0; i < 32; i++) {
                const float hv = h[i];
                const float4* wr = (const float4*)&W2m[i * 32];
                #pragma unroll
                for (int q = 0; q < 8; q++) {
                    float4 w = wr[q];
                    acc[4*q+0] = fmaf(hv, w.x, acc[4*q+0]);
                    acc[4*q+1] = fmaf(hv, w.y, acc[4*q+1]);
                    acc[4*q+2] = fmaf(hv, w.z, acc[4*q+2]);
                    acc[4*q+3] = fmaf(hv, w.w, acc[4*q+3]);
                }
            }
            #pragma unroll
            for (int o = 0; o < 32; o++) h[o] = leaky(acc[o]);
        }
        // Layer 3: 32 -> 32
        {
            float acc[32];
            #pragma unroll
            for (int o = 0; o < 32; o++) acc[o] = b3m[o];
            #pragma unroll
            for (int i = 0; i < 32; i++) {
                const float hv = h[i];
                const float4* wr = (const float4*)&W3m[i * 32];
                #pragma unroll
                for (int q = 0; q < 8; q++) {
                    float4 w = wr[q];
                    acc[4*q+0] = fmaf(hv, w.x, acc[4*q+0]);
                    acc[4*q+1] = fmaf(hv, w.y, acc[4*q+1]);
                    acc[4*q+2] = fmaf(hv, w.z, acc[4*q+2]);
                    acc[4*q+3] = fmaf(hv, w.w, acc[4*q+3]);
                }
            }
            #pragma unroll
            for (int o = 0; o < 32; o++) h[o] = leaky(acc[o]);
        }
        // Layer 4: 32 -> 1, tanh
        float o4 = b4m;
        #pragma unroll
        for (int i = 0; i < 32; i++) o4 = fmaf(h[i], W4m[i], o4);
        const float nn_out = tanhf(o4) * NN_RATIO;

        // Physics accumulation
        const float K_m = fmaf(k1, am, k0);
        Ktot = fmaf(K_m, Msm * Msm, Ktot);
        const float BF = K_m * (l0 + l1 * am - fabsf(l))
                       + k1 * l1 * am * am * nn_out;
        Bsum = fmaf(BF, Msm, Bsum);
    }

    const float invI0 = 1.0f / I0;
    const float A10 = -(Ktot + K0p) * invI0;
    const float Dd  = 2.0f * sqrtf(Ktot * I0);
    const float A11 = -(Dd + B0p) * invI0;
    const float B10 = Bsum * invI0;

    // A = [[0, DT],[A10*DT, A11*DT]]; exact closed form of the 6x6 expm:
    //   SSout = e^A * SS + phi1(A) * [0, B10*DT]^T,  phi1(A) = sum A^k/(k+1)!
    // Taylor series (||A|| <= ~0.15, 10 terms -> ~1e-13 error)
    const float a01 = DT;
    const float a10 = A10 * DT;
    const float a11 = A11 * DT;

    float T00 = 1.f, T01 = 0.f, T10 = 0.f, T11 = 1.f;   // term A^k/k!
    float E00 = 1.f, E01 = 0.f, E10 = 0.f, E11 = 1.f;   // e^A
    float P01 = 0.f, P11 = 1.f;                          // phi1 cols we need
    #pragma unroll
    for (int k = 1; k <= 10; k++) {
        const float r  = 1.0f / (float)k;
        const float n00 = (T01 * a10) * r;
        const float n01 = (T00 * a01 + T01 * a11) * r;
        const float n10 = (T11 * a10) * r;
        const float n11 = (T10 * a01 + T11 * a11) * r;
        T00 = n00; T01 = n01; T10 = n10; T11 = n11;
        E00 += T00; E01 += T01; E10 += T10; E11 += T11;
        const float r2 = 1.0f / (float)(k + 1);
        P01 = fmaf(T01, r2, P01);
        P11 = fmaf(T11, r2, P11);
    }

    const float cx = B10 * DT;
    const float o0 = E00 * ss0 + E01 * ss1 + P01 * cx;
    const float o1 = E10 * ss0 + E11 * ss1 + P11 * cx;

    // Output: ref returns (SSout[:, :1], SSout) -> concat: [B] then [B,2]
    out[b] = o0;
    ((float2*)(out + B))[b] = make_float2(o0, o1);
}

extern "C" void kernel_launch(void* const* d_in, const int* in_sizes, int n_in,
                              void* d_out, int out_size) {
    const float* SS     = (const float*)d_in[0];
    const float* Alphas = (const float*)d_in[1];
    const float* K0s    = (const float*)d_in[2];
    const float* K1s    = (const float*)d_in[3];
    const float* L0s    = (const float*)d_in[4];
    const float* L1s    = (const float*)d_in[5];
    const float* Ms     = (const float*)d_in[6];
    const float* I_p    = (const float*)d_in[7];
    const float* B_p    = (const float*)d_in[8];
    const float* K_p    = (const float*)d_in[9];
    const float* W1     = (const float*)d_in[10];
    const float* b1     = (const float*)d_in[11];
    const float* W2     = (const float*)d_in[12];
    const float* b2     = (const float*)d_in[13];
    const float* W3     = (const float*)d_in[14];
    const float* b3     = (const float*)d_in[15];
    const float* W4     = (const float*)d_in[16];
    const float* b4     = (const float*)d_in[17];
    float* out = (float*)d_out;

    const int B = in_sizes[0] / 2;
    const int grid = (B + THREADS - 1) / THREADS;
    joint1dof_kernel<<<grid, THREADS>>>(SS, Alphas, K0s, K1s, L0s, L1s, Ms,
                                        I_p, B_p, K_p, W1, b1, W2, b2, W3, b3,
                                        W4, b4, out, B);
}

// round 7
// speedup vs baseline: 1.4943x; 1.4943x over previous
#include <cuda_runtime.h>

typedef unsigned long long u64;

#define DT       0.0166667f
#define SLOPE    0.01f
#define NN_RATIO 0.5f
#define THREADS  128

// Shared-memory layout (floats), 16B-aligned sections
#define OFF_W1 0        // 2*3*32 = 192
#define OFF_B1 192      // 2*32   = 64
#define OFF_W2 256      // 2*32*32= 2048
#define OFF_B2 2304     // 64
#define OFF_W3 2368     // 2048
#define OFF_B3 4416     // 64
#define OFF_W4 4480     // 2*32   = 64
#define OFF_B4 4544     // 2
#define SM_TOTAL 4548

__device__ __forceinline__ u64 ffma2(u64 a, u64 b, u64 c) {
    u64 d;
    asm("fma.rn.f32x2 %0, %1, %2, %3;" : "=l"(d) : "l"(a), "l"(b), "l"(c));
    return d;
}
__device__ __forceinline__ u64 pack2(float lo, float hi) {
    u64 d;
    asm("mov.b64 %0, {%1, %2};" : "=l"(d) : "f"(lo), "f"(hi));
    return d;
}
__device__ __forceinline__ void unpack2(u64 p, float& lo, float& hi) {
    asm("mov.b64 {%0, %1}, %2;" : "=f"(lo), "=f"(hi) : "l"(p));
}
__device__ __forceinline__ float leaky(float x) {
    // x>=0: max(x, .01x)=x ; x<0: max(x, .01x)=.01x  -> exact leaky relu
    return fmaxf(x, SLOPE * x);
}
__device__ __forceinline__ float tanh_fast(float x) {
    float y;
    asm("tanh.approx.f32 %0, %1;" : "=f"(y) : "f"(x));
    return y;
}

// Closed-form of the 6x6 expm block structure:
//   SSout = e^A * SS + phi1(A) * [0, B10*DT]^T, phi1(A) = sum_{k>=0} A^k/(k+1)!
__device__ __forceinline__ float2 integrate(float ss0, float ss1,
                                            float Ktot, float Bsum,
                                            float invI0, float I0,
                                            float B0p, float K0p) {
    const float A10 = -(Ktot + K0p) * invI0;
    const float Dd  = 2.0f * sqrtf(Ktot * I0);
    const float A11 = -(Dd + B0p) * invI0;
    const float B10 = Bsum * invI0;

    const float a01 = DT;
    const float a10 = A10 * DT;
    const float a11 = A11 * DT;

    float T00 = 1.f, T01 = 0.f, T10 = 0.f, T11 = 1.f;
    float E00 = 1.f, E01 = 0.f, E10 = 0.f, E11 = 1.f;
    float P01 = 0.f, P11 = 1.f;
    #pragma unroll
    for (int k = 1; k <= 8; k++) {
        const float r   = 1.0f / (float)k;
        const float n00 = (T01 * a10) * r;
        const float n01 = (T00 * a01 + T01 * a11) * r;
        const float n10 = (T11 * a10) * r;
        const float n11 = (T10 * a01 + T11 * a11) * r;
        T00 = n00; T01 = n01; T10 = n10; T11 = n11;
        E00 += T00; E01 += T01; E10 += T10; E11 += T11;
        const float r2 = 1.0f / (float)(k + 1);
        P01 = fmaf(T01, r2, P01);
        P11 = fmaf(T11, r2, P11);
    }
    const float cx = B10 * DT;
    float2 o;
    o.x = E00 * ss0 + E01 * ss1 + P01 * cx;
    o.y = E10 * ss0 + E11 * ss1 + P11 * cx;
    return o;
}

__global__ void __launch_bounds__(THREADS) joint1dof_kernel(
    const float* __restrict__ SS, const float* __restrict__ Alphas,
    const float* __restrict__ K0s, const float* __restrict__ K1s,
    const float* __restrict__ L0s, const float* __restrict__ L1s,
    const float* __restrict__ Ms,  const float* __restrict__ I_p,
    const float* __restrict__ B_p, const float* __restrict__ K_p,
    const float* __restrict__ W1, const float* __restrict__ b1,
    const float* __restrict__ W2, const float* __restrict__ b2,
    const float* __restrict__ W3, const float* __restrict__ b3,
    const float* __restrict__ W4, const float* __restrict__ b4,
    float* __restrict__ out, int Bh, int B)
{
    __shared__ __align__(16) float sm[SM_TOTAL];

    const int tid = threadIdx.x;
    for (int i = tid; i < 192;  i += THREADS) sm[OFF_W1 + i] = W1[i];
    for (int i = tid; i < 64;   i += THREADS) sm[OFF_B1 + i] = b1[i];
    for (int i = tid; i < 2048; i += THREADS) sm[OFF_W2 + i] = W2[i];
    for (int i = tid; i < 64;   i += THREADS) sm[OFF_B2 + i] = b2[i];
    for (int i = tid; i < 2048; i += THREADS) sm[OFF_W3 + i] = W3[i];
    for (int i = tid; i < 64;   i += THREADS) sm[OFF_B3 + i] = b3[i];
    for (int i = tid; i < 64;   i += THREADS) sm[OFF_W4 + i] = W4[i];
    for (int i = tid; i < 2;    i += THREADS) sm[OFF_B4 + i] = b4[i];
    __syncthreads();

    const int t = blockIdx.x * THREADS + tid;
    if (t >= Bh) return;

    // Two batch elements per thread: 2t (elem0), 2t+1 (elem1)
    const float4 ssq = ((const float4*)SS)[t];      // e0:(x,y) e1:(z,w)
    const float4 alq = ((const float4*)Alphas)[t];  // e0:(x,y) e1:(z,w)

    const float I0  = __ldg(&I_p[0]);
    const float B0p = __ldg(&B_p[0]);
    const float K0p = __ldg(&K_p[0]);

    float Kt0 = 0.f, Bs0 = 0.f, Kt1 = 0.f, Bs1 = 0.f;

    #pragma unroll 1
    for (int m = 0; m < 2; m++) {
        const float Msm = __ldg(&Ms[m]);
        const float k0  = __ldg(&K0s[m]);
        const float k1  = __ldg(&K1s[m]);
        const float l0  = __ldg(&L0s[m]);
        const float l1  = __ldg(&L1s[m]);

        float ae0 = m ? alq.y : alq.x;
        float ae1 = m ? alq.w : alq.z;
        ae0 = fminf(fmaxf(ae0, 0.0f), 1.0f);
        ae1 = fminf(fmaxf(ae1, 0.0f), 1.0f);
        const float le0  = ssq.x * Msm, dle0 = ssq.y * Msm;
        const float le1  = ssq.z * Msm, dle1 = ssq.w * Msm;

        const float* W1m = &sm[OFF_W1 + m * 96];
        const float* b1m = &sm[OFF_B1 + m * 32];
        const float* W2m = &sm[OFF_W2 + m * 1024];
        const float* b2m = &sm[OFF_B2 + m * 32];
        const float* W3m = &sm[OFF_W3 + m * 1024];
        const float* b3m = &sm[OFF_B3 + m * 32];
        const float* W4m = &sm[OFF_W4 + m * 32];
        const float  b4m = sm[OFF_B4 + m];

        float h0[32], h1[32];

        // ---- Layer 1: 3 -> 32 (packed over output dim, both elements) ----
        {
            u64 acc0[16], acc1[16];
            #pragma unroll
            for (int q = 0; q < 8; q++) {
                ulonglong2 bp = ((const ulonglong2*)b1m)[q];
                acc0[2*q] = bp.x; acc0[2*q+1] = bp.y;
                acc1[2*q] = bp.x; acc1[2*q+1] = bp.y;
            }
            const float in0[3] = {le0, dle0, ae0};
            const float in1[3] = {le1, dle1, ae1};
            #pragma unroll
            for (int j = 0; j < 3; j++) {
                const u64 a0 = pack2(in0[j], in0[j]);
                const u64 a1 = pack2(in1[j], in1[j]);
                const ulonglong2* wr = (const ulonglong2*)(W1m + j * 32);
                #pragma unroll
                for (int q = 0; q < 8; q++) {
                    ulonglong2 w = wr[q];
                    acc0[2*q]   = ffma2(a0, w.x, acc0[2*q]);
                    acc0[2*q+1] = ffma2(a0, w.y, acc0[2*q+1]);
                    acc1[2*q]   = ffma2(a1, w.x, acc1[2*q]);
                    acc1[2*q+1] = ffma2(a1, w.y, acc1[2*q+1]);
                }
            }
            #pragma unroll
            for (int q = 0; q < 16; q++) {
                float x0, y0, x1, y1;
                unpack2(acc0[q], x0, y0);
                unpack2(acc1[q], x1, y1);
                h0[2*q] = leaky(x0); h0[2*q+1] = leaky(y0);
                h1[2*q] = leaky(x1); h1[2*q+1] = leaky(y1);
            }
        }

        // ---- Layers 2 & 3: 32 -> 32 (one code copy, weights reused for both elems) ----
        #pragma unroll 1
        for (int L = 0; L < 2; L++) {
            const float* Wm = L ? W3m : W2m;
            const float* bm = L ? b3m : b2m;
            u64 acc0[16], acc1[16];
            #pragma unroll
            for (int q = 0; q < 8; q++) {
                ulonglong2 bp = ((const ulonglong2*)bm)[q];
                acc0[2*q] = bp.x; acc0[2*q+1] = bp.y;
                acc1[2*q] = bp.x; acc1[2*q+1] = bp.y;
            }
            #pragma unroll
            for (int i = 0; i < 32; i++) {
                const u64 a0 = pack2(h0[i], h0[i]);
                const u64 a1 = pack2(h1[i], h1[i]);
                const ulonglong2* wr = (const ulonglong2*)(Wm + i * 32);
                #pragma unroll
                for (int q = 0; q < 8; q++) {
                    ulonglong2 w = wr[q];
                    acc0[2*q]   = ffma2(a0, w.x, acc0[2*q]);
                    acc0[2*q+1] = ffma2(a0, w.y, acc0[2*q+1]);
                    acc1[2*q]   = ffma2(a1, w.x, acc1[2*q]);
                    acc1[2*q+1] = ffma2(a1, w.y, acc1[2*q+1]);
                }
            }
            #pragma unroll
            for (int q = 0; q < 16; q++) {
                float x0, y0, x1, y1;
                unpack2(acc0[q], x0, y0);
                unpack2(acc1[q], x1, y1);
                h0[2*q] = leaky(x0); h0[2*q+1] = leaky(y0);
                h1[2*q] = leaky(x1); h1[2*q+1] = leaky(y1);
            }
        }

        // ---- Layer 4: 32 -> 1, tanh ----
        float nn0, nn1;
        {
            u64 p0 = 0ull, p1 = 0ull;
            const ulonglong2* wr = (const ulonglong2*)W4m;
            #pragma unroll
            for (int q = 0; q < 8; q++) {
                ulonglong2 w = wr[q];
                p0 = ffma2(pack2(h0[4*q],   h0[4*q+1]), w.x, p0);
                p0 = ffma2(pack2(h0[4*q+2], h0[4*q+3]), w.y, p0);
                p1 = ffma2(pack2(h1[4*q],   h1[4*q+1]), w.x, p1);
                p1 = ffma2(pack2(h1[4*q+2], h1[4*q+3]), w.y, p1);
            }
            float px, py;
            unpack2(p0, px, py);
            nn0 = tanh_fast(px + py + b4m) * NN_RATIO;
            unpack2(p1, px, py);
            nn1 = tanh_fast(px + py + b4m) * NN_RATIO;
        }

        // ---- Physics accumulation ----
        const float Ms2 = Msm * Msm;
        const float Km0 = fmaf(k1, ae0, k0);
        Kt0 = fmaf(Km0, Ms2, Kt0);
        const float BF0 = Km0 * (l0 + l1 * ae0 - fabsf(le0))
                        + k1 * l1 * ae0 * ae0 * nn0;
        Bs0 = fmaf(BF0, Msm, Bs0);

        const float Km1 = fmaf(k1, ae1, k0);
        Kt1 = fmaf(Km1, Ms2, Kt1);
        const float BF1 = Km1 * (l0 + l1 * ae1 - fabsf(le1))
                        + k1 * l1 * ae1 * ae1 * nn1;
        Bs1 = fmaf(BF1, Msm, Bs1);
    }

    const float invI0 = 1.0f / I0;
    const float2 r0 = integrate(ssq.x, ssq.y, Kt0, Bs0, invI0, I0, B0p, K0p);
    const float2 r1 = integrate(ssq.z, ssq.w, Kt1, Bs1, invI0, I0, B0p, K0p);

    // Output: [B] first component, then [B,2] full state
    ((float2*)out)[t] = make_float2(r0.x, r1.x);
    ((float4*)(out + B))[t] = make_float4(r0.x, r0.y, r1.x, r1.y);
}

extern "C" void kernel_launch(void* const* d_in, const int* in_sizes, int n_in,
                              void* d_out, int out_size) {
    const float* SS     = (const float*)d_in[0];
    const float* Alphas = (const float*)d_in[1];
    const float* K0s    = (const float*)d_in[2];
    const float* K1s    = (const float*)d_in[3];
    const float* L0s    = (const float*)d_in[4];
    const float* L1s    = (const float*)d_in[5];
    const float* Ms     = (const float*)d_in[6];
    const float* I_p    = (const float*)d_in[7];
    const float* B_p    = (const float*)d_in[8];
    const float* K_p    = (const float*)d_in[9];
    const float* W1     = (const float*)d_in[10];
    const float* b1     = (const float*)d_in[11];
    const float* W2     = (const float*)d_in[12];
    const float* b2     = (const float*)d_in[13];
    const float* W3     = (const float*)d_in[14];
    const float* b3     = (const float*)d_in[15];
    const float* W4     = (const float*)d_in[16];
    const float* b4     = (const float*)d_in[17];
    float* out = (float*)d_out;

    const int B  = in_sizes[0] / 2;
    const int Bh = B / 2;  // two elements per thread
    const int grid = (Bh + THREADS - 1) / THREADS;
    joint1dof_kernel<<<grid, THREADS>>>(SS, Alphas, K0s, K1s, L0s, L1s, Ms,
                                        I_p, B_p, K_p, W1, b1, W2, b2, W3, b3,
                                        W4, b4, out, Bh, B);
}

// round 10
// speedup vs baseline: 1.5630x; 1.0460x over previous
#include <cuda_runtime.h>

typedef unsigned long long u64;

#define DT       0.0166667f
#define SLOPE    0.01f
#define NN_RATIO 0.5f
#define THREADS  64

// Shared-memory layout (floats), 16B-aligned sections
#define OFF_W1 0        // 2*3*32 = 192
#define OFF_B1 192      // 2*32   = 64
#define OFF_W2 256      // 2*32*32= 2048
#define OFF_B2 2304     // 64
#define OFF_W3 2368     // 2048
#define OFF_B3 4416     // 64
#define OFF_W4 4480     // 2*32   = 64
#define OFF_B4 4544     // 2
#define SM_TOTAL 4548

__device__ __forceinline__ u64 ffma2(u64 a, u64 b, u64 c) {
    u64 d;
    asm("fma.rn.f32x2 %0, %1, %2, %3;" : "=l"(d) : "l"(a), "l"(b), "l"(c));
    return d;
}
__device__ __forceinline__ u64 pack2(float lo, float hi) {
    u64 d;
    asm("mov.b64 %0, {%1, %2};" : "=l"(d) : "f"(lo), "f"(hi));
    return d;
}
__device__ __forceinline__ void unpack2(u64 p, float& lo, float& hi) {
    asm("mov.b64 {%0, %1}, %2;" : "=f"(lo), "=f"(hi) : "l"(p));
}
__device__ __forceinline__ float leaky(float x) {
    return fmaxf(x, SLOPE * x);
}
__device__ __forceinline__ float tanh_fast(float x) {
    float y;
    asm("tanh.approx.f32 %0, %1;" : "=f"(y) : "f"(x));
    return y;
}

// Closed-form of the 6x6 expm block structure:
//   SSout = e^A * SS + phi1(A) * [0, B10*DT]^T, phi1(A) = sum_{k>=0} A^k/(k+1)!
__device__ __forceinline__ float2 integrate(float ss0, float ss1,
                                            float Ktot, float Bsum,
                                            float invI0, float I0,
                                            float B0p, float K0p) {
    const float A10 = -(Ktot + K0p) * invI0;
    const float Dd  = 2.0f * sqrtf(Ktot * I0);
    const float A11 = -(Dd + B0p) * invI0;
    const float B10 = Bsum * invI0;

    const float a01 = DT;
    const float a10 = A10 * DT;
    const float a11 = A11 * DT;

    float T00 = 1.f, T01 = 0.f, T10 = 0.f, T11 = 1.f;
    float E00 = 1.f, E01 = 0.f, E10 = 0.f, E11 = 1.f;
    float P01 = 0.f, P11 = 1.f;
    #pragma unroll
    for (int k = 1; k <= 8; k++) {
        const float r   = 1.0f / (float)k;
        const float n00 = (T01 * a10) * r;
        const float n01 = (T00 * a01 + T01 * a11) * r;
        const float n10 = (T11 * a10) * r;
        const float n11 = (T10 * a01 + T11 * a11) * r;
        T00 = n00; T01 = n01; T10 = n10; T11 = n11;
        E00 += T00; E01 += T01; E10 += T10; E11 += T11;
        const float r2 = 1.0f / (float)(k + 1);
        P01 = fmaf(T01, r2, P01);
        P11 = fmaf(T11, r2, P11);
    }
    const float cx = B10 * DT;
    float2 o;
    o.x = E00 * ss0 + E01 * ss1 + P01 * cx;
    o.y = E10 * ss0 + E11 * ss1 + P11 * cx;
    return o;
}

__global__ void __launch_bounds__(THREADS, 6) joint1dof_kernel(
    const float* __restrict__ SS, const float* __restrict__ Alphas,
    const float* __restrict__ K0s, const float* __restrict__ K1s,
    const float* __restrict__ L0s, const float* __restrict__ L1s,
    const float* __restrict__ Ms,  const float* __restrict__ I_p,
    const float* __restrict__ B_p, const float* __restrict__ K_p,
    const float* __restrict__ W1, const float* __restrict__ b1,
    const float* __restrict__ W2, const float* __restrict__ b2,
    const float* __restrict__ W3, const float* __restrict__ b3,
    const float* __restrict__ W4, const float* __restrict__ b4,
    float* __restrict__ out, int Bh, int B)
{
    __shared__ __align__(16) float sm[SM_TOTAL];

    const int tid = threadIdx.x;
    for (int i = tid; i < 192;  i += THREADS) sm[OFF_W1 + i] = W1[i];
    for (int i = tid; i < 64;   i += THREADS) sm[OFF_B1 + i] = b1[i];
    for (int i = tid; i < 2048; i += THREADS) sm[OFF_W2 + i] = W2[i];
    for (int i = tid; i < 64;   i += THREADS) sm[OFF_B2 + i] = b2[i];
    for (int i = tid; i < 2048; i += THREADS) sm[OFF_W3 + i] = W3[i];
    for (int i = tid; i < 64;   i += THREADS) sm[OFF_B3 + i] = b3[i];
    for (int i = tid; i < 64;   i += THREADS) sm[OFF_W4 + i] = W4[i];
    for (int i = tid; i < 2;    i += THREADS) sm[OFF_B4 + i] = b4[i];
    __syncthreads();

    const int t = blockIdx.x * THREADS + tid;
    if (t >= Bh) return;

    // Two batch elements per thread: 2t (elem0), 2t+1 (elem1)
    const float4 ssq = ((const float4*)SS)[t];      // e0:(x,y) e1:(z,w)
    const float4 alq = ((const float4*)Alphas)[t];  // e0:(x,y) e1:(z,w)

    const float I0  = __ldg(&I_p[0]);
    const float B0p = __ldg(&B_p[0]);
    const float K0p = __ldg(&K_p[0]);

    float Kt0 = 0.f, Bs0 = 0.f, Kt1 = 0.f, Bs1 = 0.f;

    #pragma unroll 1
    for (int m = 0; m < 2; m++) {
        const float Msm = __ldg(&Ms[m]);
        const float k0  = __ldg(&K0s[m]);
        const float k1  = __ldg(&K1s[m]);
        const float l0  = __ldg(&L0s[m]);
        const float l1  = __ldg(&L1s[m]);

        const float ae0 = __saturatef(m ? alq.y : alq.x);
        const float ae1 = __saturatef(m ? alq.w : alq.z);
        const float le0  = ssq.x * Msm, dle0 = ssq.y * Msm;
        const float le1  = ssq.z * Msm, dle1 = ssq.w * Msm;

        const float* W1m = &sm[OFF_W1 + m * 96];
        const float* b1m = &sm[OFF_B1 + m * 32];
        const float* W2m = &sm[OFF_W2 + m * 1024];
        const float* b2m = &sm[OFF_B2 + m * 32];
        const float* W3m = &sm[OFF_W3 + m * 1024];
        const float* b3m = &sm[OFF_B3 + m * 32];
        const float* W4m = &sm[OFF_W4 + m * 32];
        const float  b4m = sm[OFF_B4 + m];

        float h0[32], h1[32];

        // ---- Layer 1: 3 -> 32 (packed over output dim, both elements) ----
        {
            u64 acc0[16], acc1[16];
            #pragma unroll
            for (int q = 0; q < 8; q++) {
                ulonglong2 bp = ((const ulonglong2*)b1m)[q];
                acc0[2*q] = bp.x; acc0[2*q+1] = bp.y;
                acc1[2*q] = bp.x; acc1[2*q+1] = bp.y;
            }
            const float in0[3] = {le0, dle0, ae0};
            const float in1[3] = {le1, dle1, ae1};
            #pragma unroll
            for (int j = 0; j < 3; j++) {
                const u64 a0 = pack2(in0[j], in0[j]);
                const u64 a1 = pack2(in1[j], in1[j]);
                const ulonglong2* wr = (const ulonglong2*)(W1m + j * 32);
                #pragma unroll
                for (int q = 0; q < 8; q++) {
                    ulonglong2 w = wr[q];
                    acc0[2*q]   = ffma2(a0, w.x, acc0[2*q]);
                    acc0[2*q+1] = ffma2(a0, w.y, acc0[2*q+1]);
                    acc1[2*q]   = ffma2(a1, w.x, acc1[2*q]);
                    acc1[2*q+1] = ffma2(a1, w.y, acc1[2*q+1]);
                }
            }
            #pragma unroll
            for (int q = 0; q < 16; q++) {
                float x0, y0, x1, y1;
                unpack2(acc0[q], x0, y0);
                unpack2(acc1[q], x1, y1);
                h0[2*q] = leaky(x0); h0[2*q+1] = leaky(y0);
                h1[2*q] = leaky(x1); h1[2*q+1] = leaky(y1);
            }
        }

        // ---- Layers 2 & 3: 32 -> 32 (one code copy, weights reused for both elems) ----
        #pragma unroll 1
        for (int L = 0; L < 2; L++) {
            const float* Wm = L ? W3m : W2m;
            const float* bm = L ? b3m : b2m;
            u64 acc0[16], acc1[16];
            #pragma unroll
            for (int q = 0; q < 8; q++) {
                ulonglong2 bp = ((const ulonglong2*)bm)[q];
                acc0[2*q] = bp.x; acc0[2*q+1] = bp.y;
                acc1[2*q] = bp.x; acc1[2*q+1] = bp.y;
            }
            #pragma unroll
            for (int i = 0; i < 32; i++) {
                const u64 a0 = pack2(h0[i], h0[i]);
                const u64 a1 = pack2(h1[i], h1[i]);
                const ulonglong2* wr = (const ulonglong2*)(Wm + i * 32);
                #pragma unroll
                for (int q = 0; q < 8; q++) {
                    ulonglong2 w = wr[q];
                    acc0[2*q]   = ffma2(a0, w.x, acc0[2*q]);
                    acc0[2*q+1] = ffma2(a0, w.y, acc0[2*q+1]);
                    acc1[2*q]   = ffma2(a1, w.x, acc1[2*q]);
                    acc1[2*q+1] = ffma2(a1, w.y, acc1[2*q+1]);
                }
            }
            #pragma unroll
            for (int q = 0; q < 16; q++) {
                float x0, y0, x1, y1;
                unpack2(acc0[q], x0, y0);
                unpack2(acc1[q], x1, y1);
                h0[2*q] = leaky(x0); h0[2*q+1] = leaky(y0);
                h1[2*q] = leaky(x1); h1[2*q+1] = leaky(y1);
            }
        }

        // ---- Layer 4: 32 -> 1, tanh ----
        float nn0, nn1;
        {
            u64 p0 = 0ull, p1 = 0ull;
            const ulonglong2* wr = (const ulonglong2*)W4m;
            #pragma unroll
            for (int q = 0; q < 8; q++) {
                ulonglong2 w = wr[q];
                p0 = ffma2(pack2(h0[4*q],   h0[4*q+1]), w.x, p0);
                p0 = ffma2(pack2(h0[4*q+2], h0[4*q+3]), w.y, p0);
                p1 = ffma2(pack2(h1[4*q],   h1[4*q+1]), w.x, p1);
                p1 = ffma2(pack2(h1[4*q+2], h1[4*q+3]), w.y, p1);
            }
            float px, py;
            unpack2(p0, px, py);
            nn0 = tanh_fast(px + py + b4m) * NN_RATIO;
            unpack2(p1, px, py);
            nn1 = tanh_fast(px + py + b4m) * NN_RATIO;
        }

        // ---- Physics accumulation ----
        const float Ms2 = Msm * Msm;
        const float Km0 = fmaf(k1, ae0, k0);
        Kt0 = fmaf(Km0, Ms2, Kt0);
        const float BF0 = Km0 * (l0 + l1 * ae0 - fabsf(le0))
                        + k1 * l1 * ae0 * ae0 * nn0;
        Bs0 = fmaf(BF0, Msm, Bs0);

        const float Km1 = fmaf(k1, ae1, k0);
        Kt1 = fmaf(Km1, Ms2, Kt1);
        const float BF1 = Km1 * (l0 + l1 * ae1 - fabsf(le1))
                        + k1 * l1 * ae1 * ae1 * nn1;
        Bs1 = fmaf(BF1, Msm, Bs1);
    }

    const float invI0 = 1.0f / I0;
    const float2 r0 = integrate(ssq.x, ssq.y, Kt0, Bs0, invI0, I0, B0p, K0p);
    const float2 r1 = integrate(ssq.z, ssq.w, Kt1, Bs1, invI0, I0, B0p, K0p);

    // Output: [B] first component, then [B,2] full state
    ((float2*)out)[t] = make_float2(r0.x, r1.x);
    ((float4*)(out + B))[t] = make_float4(r0.x, r0.y, r1.x, r1.y);
}

extern "C" void kernel_launch(void* const* d_in, const int* in_sizes, int n_in,
                              void* d_out, int out_size) {
    const float* SS     = (const float*)d_in[0];
    const float* Alphas = (const float*)d_in[1];
    const float* K0s    = (const float*)d_in[2];
    const float* K1s    = (const float*)d_in[3];
    const float* L0s    = (const float*)d_in[4];
    const float* L1s    = (const float*)d_in[5];
    const float* Ms     = (const float*)d_in[6];
    const float* I_p    = (const float*)d_in[7];
    const float* B_p    = (const float*)d_in[8];
    const float* K_p    = (const float*)d_in[9];
    const float* W1     = (const float*)d_in[10];
    const float* b1     = (const float*)d_in[11];
    const float* W2     = (const float*)d_in[12];
    const float* b2     = (const float*)d_in[13];
    const float* W3     = (const float*)d_in[14];
    const float* b3     = (const float*)d_in[15];
    const float* W4     = (const float*)d_in[16];
    const float* b4     = (const float*)d_in[17];
    float* out = (float*)d_out;

    const int B  = in_sizes[0] / 2;
    const int Bh = B / 2;  // two elements per thread
    const int grid = (Bh + THREADS - 1) / THREADS;
    joint1dof_kernel<<<grid, THREADS>>>(SS, Alphas, K0s, K1s, L0s, L1s, Ms,
                                        I_p, B_p, K_p, W1, b1, W2, b2, W3, b3,
                                        W4, b4, out, Bh, B);
}

// round 11
// speedup vs baseline: 4.1837x; 2.6767x over previous
#include <cuda_runtime.h>
#include <cuda_bf16.h>
#include <cstdint>

#define DT       0.0166667f
#define SLOPE    0.01f
#define NN_RATIO 0.5f
#define THREADS  128
#define PASSES   4

struct __align__(16) Smem {
    __nv_bfloat16 wt1[2][32][20];   // W1^T padded: [m][o][k<16], k>=3 zero
    __nv_bfloat16 wt2[2][32][40];   // W2^T padded: [m][o][i]
    __nv_bfloat16 wt3[2][32][40];   // W3^T padded
    float b1[2][32], b2[2][32], b3[2][32], w4[2][32], b4[2];
};

__device__ __forceinline__ float leaky(float x) { return fmaxf(x, SLOPE * x); }
__device__ __forceinline__ float tanh_fast(float x) {
    float y; asm("tanh.approx.f32 %0, %1;" : "=f"(y) : "f"(x)); return y;
}
// pack two f32 -> bf16x2 (lo in low half)
__device__ __forceinline__ uint32_t pkbf(float lo, float hi) {
    uint32_t r; asm("cvt.rn.bf16x2.f32 %0, %1, %2;" : "=r"(r) : "f"(hi), "f"(lo)); return r;
}
__device__ __forceinline__ void mma16816(float* d,
    uint32_t a0, uint32_t a1, uint32_t a2, uint32_t a3,
    uint32_t b0, uint32_t b1,
    float c0, float c1, float c2, float c3)
{
    asm volatile(
        "mma.sync.aligned.m16n8k16.row.col.f32.bf16.bf16.f32 "
        "{%0,%1,%2,%3},{%4,%5,%6,%7},{%8,%9},{%10,%11,%12,%13};"
        : "=f"(d[0]), "=f"(d[1]), "=f"(d[2]), "=f"(d[3])
        : "r"(a0), "r"(a1), "r"(a2), "r"(a3), "r"(b0), "r"(b1),
          "f"(c0), "f"(c1), "f"(c2), "f"(c3));
}

// SSout = e^A*SS + phi1(A)*[0, B10*DT]^T  (closed form of the 6x6 expm)
__device__ __forceinline__ float2 integrate(float ss0, float ss1, float Ktot, float Bsum,
                                            float invI0, float I0, float B0p, float K0p) {
    const float A10 = -(Ktot + K0p) * invI0;
    const float Dd  = 2.0f * sqrtf(Ktot * I0);
    const float A11 = -(Dd + B0p) * invI0;
    const float B10 = Bsum * invI0;
    const float a01 = DT, a10 = A10 * DT, a11 = A11 * DT;

    float T00 = 1.f, T01 = 0.f, T10 = 0.f, T11 = 1.f;
    float E00 = 1.f, E01 = 0.f, E10 = 0.f, E11 = 1.f;
    float P01 = 0.f, P11 = 1.f;
    #pragma unroll
    for (int k = 1; k <= 8; k++) {
        const float r   = 1.0f / (float)k;
        const float n00 = (T01 * a10) * r;
        const float n01 = (T00 * a01 + T01 * a11) * r;
        const float n10 = (T11 * a10) * r;
        const float n11 = (T10 * a01 + T11 * a11) * r;
        T00 = n00; T01 = n01; T10 = n10; T11 = n11;
        E00 += T00; E01 += T01; E10 += T10; E11 += T11;
        const float r2 = 1.0f / (float)(k + 1);
        P01 = fmaf(T01, r2, P01);
        P11 = fmaf(T11, r2, P11);
    }
    const float cx = B10 * DT;
    float2 o;
    o.x = E00 * ss0 + E01 * ss1 + P01 * cx;
    o.y = E10 * ss0 + E11 * ss1 + P11 * cx;
    return o;
}

__global__ void __launch_bounds__(THREADS, 3) joint_mma_kernel(
    const float* __restrict__ SS, const float* __restrict__ Alphas,
    const float* __restrict__ K0s, const float* __restrict__ K1s,
    const float* __restrict__ L0s, const float* __restrict__ L1s,
    const float* __restrict__ Ms,  const float* __restrict__ I_p,
    const float* __restrict__ B_p, const float* __restrict__ K_p,
    const float* __restrict__ W1, const float* __restrict__ b1g,
    const float* __restrict__ W2, const float* __restrict__ b2g,
    const float* __restrict__ W3, const float* __restrict__ b3g,
    const float* __restrict__ W4, const float* __restrict__ b4g,
    float* __restrict__ out, int B)
{
    __shared__ Smem sm;
    const int tid = threadIdx.x;

    // ---- Stage weights (transposed, bf16) + biases (f32) ----
    for (int idx = tid; idx < 1024; idx += THREADS) {   // wt1: m,o,k16
        const int k = idx & 15, o = (idx >> 4) & 31, m = idx >> 9;
        const float v = (k < 3) ? W1[m * 96 + k * 32 + o] : 0.0f;
        sm.wt1[m][o][k] = __float2bfloat16(v);
    }
    for (int idx = tid; idx < 2048; idx += THREADS) {   // wt2/wt3
        const int o = idx & 31, i = (idx >> 5) & 31, m = idx >> 10;
        sm.wt2[m][o][i] = __float2bfloat16(W2[idx]);
        sm.wt3[m][o][i] = __float2bfloat16(W3[idx]);
    }
    for (int idx = tid; idx < 64; idx += THREADS) {
        const int m = idx >> 5, o = idx & 31;
        sm.b1[m][o] = b1g[idx];
        sm.b2[m][o] = b2g[idx];
        sm.b3[m][o] = b3g[idx];
        sm.w4[m][o] = W4[idx];
    }
    if (tid < 2) sm.b4[tid] = b4g[tid];
    __syncthreads();

    const int l  = tid & 31, w = tid >> 5;
    const int g  = l >> 2, tc = l & 3;
    const int own_row = g + 8 * tc;

    // uniform scalars
    const float I0  = __ldg(I_p), B0p = __ldg(B_p), K0p = __ldg(K_p);
    const float invI0 = 1.0f / I0;
    const float Msv[2] = {__ldg(Ms),      __ldg(Ms + 1)};
    const float k0v[2] = {__ldg(K0s),     __ldg(K0s + 1)};
    const float k1v[2] = {__ldg(K1s),     __ldg(K1s + 1)};
    const float l0v[2] = {__ldg(L0s),     __ldg(L0s + 1)};
    const float l1v[2] = {__ldg(L1s),     __ldg(L1s + 1)};

    #pragma unroll 1
    for (int p = 0; p < PASSES; p++) {
        const int ebase = (blockIdx.x * PASSES + p) * 128 + w * 32;
        const int e = ebase + own_row;
        const float2 ss = ((const float2*)SS)[e];
        const float2 al = ((const float2*)Alphas)[e];
        const float al0 = __saturatef(al.x);
        const float al1 = __saturatef(al.y);

        // gather rows g+8j for A-fragment construction (j = 0..3)
        float s0[4], s1[4], am0[4], am1[4];
        #pragma unroll
        for (int j = 0; j < 4; j++) {
            const int src = (l & ~3) + j;
            s0[j]  = __shfl_sync(0xffffffffu, ss.x, src);
            s1[j]  = __shfl_sync(0xffffffffu, ss.y, src);
            am0[j] = __shfl_sync(0xffffffffu, al0, src);
            am1[j] = __shfl_sync(0xffffffffu, al1, src);
        }

        float Kt = 0.f, Bs = 0.f;

        #pragma unroll
        for (int m = 0; m < 2; m++) {
            const float Msm = Msv[m], k0 = k0v[m], k1 = k1v[m], l0 = l0v[m], l1 = l1v[m];

            // ---- Layer 1 A-fragments: X = [l, dl, alpha, 0...] rows ----
            uint32_t A1f[2][2];   // [mt][a0/a1]
            #pragma unroll
            for (int mt = 0; mt < 2; mt++) {
                #pragma unroll
                for (int jj = 0; jj < 2; jj++) {
                    const int j = 2 * mt + jj;
                    float x0 = 0.f, x1 = 0.f;
                    if (tc == 0)      { x0 = s0[j] * Msm; x1 = s1[j] * Msm; }
                    else if (tc == 1) { x0 = (m ? am1[j] : am0[j]); }
                    A1f[mt][jj] = pkbf(x0, x1);
                }
            }

            float d[2][4][4];

            // ---- Layer 1 mma: K=16 (one ktile), bias as C ----
            #pragma unroll
            for (int nt = 0; nt < 4; nt++) {
                const int n = nt * 8 + g;
                const float2 bias = *(const float2*)&sm.b1[m][nt * 8 + 2 * tc];
                const uint32_t b0 = *(const uint32_t*)&sm.wt1[m][n][2 * tc];
                const uint32_t b1f = *(const uint32_t*)&sm.wt1[m][n][2 * tc + 8];
                #pragma unroll
                for (int mt = 0; mt < 2; mt++)
                    mma16816(d[mt][nt], A1f[mt][0], A1f[mt][1], 0u, 0u,
                             b0, b1f, bias.x, bias.y, bias.x, bias.y);
            }

            // ---- Layers 2 and 3 ----
            #pragma unroll
            for (int L = 0; L < 2; L++) {
                // leaky + pack D -> A fragments (D(m16n8) layout == A(m16k16) layout)
                uint32_t A2[2][2][4];   // [mt][kt][4]
                #pragma unroll
                for (int mt = 0; mt < 2; mt++) {
                    #pragma unroll
                    for (int kt = 0; kt < 2; kt++) {
                        const int na = 2 * kt, nb = 2 * kt + 1;
                        A2[mt][kt][0] = pkbf(leaky(d[mt][na][0]), leaky(d[mt][na][1]));
                        A2[mt][kt][1] = pkbf(leaky(d[mt][na][2]), leaky(d[mt][na][3]));
                        A2[mt][kt][2] = pkbf(leaky(d[mt][nb][0]), leaky(d[mt][nb][1]));
                        A2[mt][kt][3] = pkbf(leaky(d[mt][nb][2]), leaky(d[mt][nb][3]));
                    }
                }
                const __nv_bfloat16 (*wt)[32][40] = L ? sm.wt3 : sm.wt2;
                const float (*bb)[32] = L ? sm.b3 : sm.b2;
                #pragma unroll
                for (int nt = 0; nt < 4; nt++) {
                    const int n = nt * 8 + g;
                    const float2 bias = *(const float2*)&bb[m][nt * 8 + 2 * tc];
                    const uint32_t b00 = *(const uint32_t*)&wt[m][n][2 * tc];
                    const uint32_t b01 = *(const uint32_t*)&wt[m][n][2 * tc + 8];
                    const uint32_t b10 = *(const uint32_t*)&wt[m][n][2 * tc + 16];
                    const uint32_t b11 = *(const uint32_t*)&wt[m][n][2 * tc + 24];
                    #pragma unroll
                    for (int mt = 0; mt < 2; mt++) {
                        mma16816(d[mt][nt], A2[mt][0][0], A2[mt][0][1], A2[mt][0][2], A2[mt][0][3],
                                 b00, b01, bias.x, bias.y, bias.x, bias.y);
                        mma16816(d[mt][nt], A2[mt][1][0], A2[mt][1][1], A2[mt][1][2], A2[mt][1][3],
                                 b10, b11, d[mt][nt][0], d[mt][nt][1], d[mt][nt][2], d[mt][nt][3]);
                    }
                }
            }

            // ---- Layer 4: per-lane partial dots over its 8 cols x 4 rows ----
            float p0 = 0.f, p1 = 0.f, p2 = 0.f, p3 = 0.f;
            #pragma unroll
            for (int nt = 0; nt < 4; nt++) {
                const float2 w4p = *(const float2*)&sm.w4[m][nt * 8 + 2 * tc];
                p0 = fmaf(leaky(d[0][nt][0]), w4p.x, fmaf(leaky(d[0][nt][1]), w4p.y, p0));
                p1 = fmaf(leaky(d[0][nt][2]), w4p.x, fmaf(leaky(d[0][nt][3]), w4p.y, p1));
                p2 = fmaf(leaky(d[1][nt][0]), w4p.x, fmaf(leaky(d[1][nt][1]), w4p.y, p2));
                p3 = fmaf(leaky(d[1][nt][2]), w4p.x, fmaf(leaky(d[1][nt][3]), w4p.y, p3));
            }
            // butterfly reduce within the 4-lane col group
            p0 += __shfl_xor_sync(0xffffffffu, p0, 1);
            p0 += __shfl_xor_sync(0xffffffffu, p0, 2);
            p1 += __shfl_xor_sync(0xffffffffu, p1, 1);
            p1 += __shfl_xor_sync(0xffffffffu, p1, 2);
            p2 += __shfl_xor_sync(0xffffffffu, p2, 1);
            p2 += __shfl_xor_sync(0xffffffffu, p2, 2);
            p3 += __shfl_xor_sync(0xffffffffu, p3, 1);
            p3 += __shfl_xor_sync(0xffffffffu, p3, 2);
            // own row = g + 8*tc  ->  pick p[tc]
            const float o4 = (tc & 2) ? ((tc & 1) ? p3 : p2) : ((tc & 1) ? p1 : p0);
            const float nn = tanh_fast(o4 + sm.b4[m]) * NN_RATIO;

            // ---- physics for own element (fp32) ----
            const float amv = m ? al1 : al0;
            const float lo  = ss.x * Msm;
            const float Km  = fmaf(k1, amv, k0);
            Kt = fmaf(Km, Msm * Msm, Kt);
            const float BF = Km * (l0 + l1 * amv - fabsf(lo))
                           + k1 * l1 * amv * amv * nn;
            Bs = fmaf(BF, Msm, Bs);
        }

        const float2 rr = integrate(ss.x, ss.y, Kt, Bs, invI0, I0, B0p, K0p);
        out[e] = rr.x;
        ((float2*)(out + B))[e] = rr;
    }
}

extern "C" void kernel_launch(void* const* d_in, const int* in_sizes, int n_in,
                              void* d_out, int out_size) {
    const float* SS     = (const float*)d_in[0];
    const float* Alphas = (const float*)d_in[1];
    const float* K0s    = (const float*)d_in[2];
    const float* K1s    = (const float*)d_in[3];
    const float* L0s    = (const float*)d_in[4];
    const float* L1s    = (const float*)d_in[5];
    const float* Ms     = (const float*)d_in[6];
    const float* I_p    = (const float*)d_in[7];
    const float* B_p    = (const float*)d_in[8];
    const float* K_p    = (const float*)d_in[9];
    const float* W1     = (const float*)d_in[10];
    const float* b1     = (const float*)d_in[11];
    const float* W2     = (const float*)d_in[12];
    const float* b2     = (const float*)d_in[13];
    const float* W3     = (const float*)d_in[14];
    const float* b3     = (const float*)d_in[15];
    const float* W4     = (const float*)d_in[16];
    const float* b4     = (const float*)d_in[17];
    float* out = (float*)d_out;

    const int B = in_sizes[0] / 2;
    const int grid = B / (128 * PASSES);
    joint_mma_kernel<<<grid, THREADS>>>(SS, Alphas, K0s, K1s, L0s, L1s, Ms,
                                        I_p, B_p, K_p, W1, b1, W2, b2, W3, b3,
                                        W4, b4, out, B);
}

// round 12
// speedup vs baseline: 4.4605x; 1.0661x over previous
#include <cuda_runtime.h>
#include <cuda_bf16.h>
#include <cstdint>

#define DT       0.0166667f
#define SLOPE    0.01f
#define NN_RATIO 0.5f
#define THREADS  128
#define PASSES   4

// bf16x2 constant 0.01 (0x3C24 per half)
#define SLOPE2   0x3C243C24u

struct __align__(16) Smem {
    __nv_bfloat16 wt1[2][32][20];   // W1^T padded, Ms folded into k=0,1; k>=3 zero
    __nv_bfloat16 wt2[2][32][40];   // W2^T padded: [m][o][i]
    __nv_bfloat16 wt3[2][32][40];   // W3^T padded
    float b1[2][32], b2[2][32], b3[2][32], w4[2][32], b4[2];
};

__device__ __forceinline__ float leaky(float x) { return fmaxf(x, SLOPE * x); }
__device__ __forceinline__ float tanh_fast(float x) {
    float y; asm("tanh.approx.f32 %0, %1;" : "=f"(y) : "f"(x)); return y;
}
// pack two f32 -> bf16x2 (lo in low half)
__device__ __forceinline__ uint32_t pkbf(float lo, float hi) {
    uint32_t r; asm("cvt.rn.bf16x2.f32 %0, %1, %2;" : "=r"(r) : "f"(hi), "f"(lo)); return r;
}
// packed leaky relu on bf16x2: max(x, 0.01*x)
__device__ __forceinline__ uint32_t lk2(uint32_t x) {
    uint32_t y, r;
    asm("mul.rn.bf16x2 %0, %1, %2;" : "=r"(y) : "r"(x), "r"(SLOPE2));
    asm("max.bf16x2 %0, %1, %2;"    : "=r"(r) : "r"(x), "r"(y));
    return r;
}
// leaky(f32 pair) -> bf16x2 packed
__device__ __forceinline__ uint32_t lkpk(float a, float b) { return lk2(pkbf(a, b)); }

__device__ __forceinline__ void mma16816(float* d,
    uint32_t a0, uint32_t a1, uint32_t a2, uint32_t a3,
    uint32_t b0, uint32_t b1,
    float c0, float c1, float c2, float c3)
{
    asm volatile(
        "mma.sync.aligned.m16n8k16.row.col.f32.bf16.bf16.f32 "
        "{%0,%1,%2,%3},{%4,%5,%6,%7},{%8,%9},{%10,%11,%12,%13};"
        : "=f"(d[0]), "=f"(d[1]), "=f"(d[2]), "=f"(d[3])
        : "r"(a0), "r"(a1), "r"(a2), "r"(a3), "r"(b0), "r"(b1),
          "f"(c0), "f"(c1), "f"(c2), "f"(c3));
}

// SSout = e^A*SS + phi1(A)*[0, B10*DT]^T  (closed form of the 6x6 expm)
__device__ __forceinline__ float2 integrate(float ss0, float ss1, float Ktot, float Bsum,
                                            float invI0, float I0, float B0p, float K0p) {
    const float A10 = -(Ktot + K0p) * invI0;
    const float Dd  = 2.0f * sqrtf(Ktot * I0);
    const float A11 = -(Dd + B0p) * invI0;
    const float B10 = Bsum * invI0;
    const float a01 = DT, a10 = A10 * DT, a11 = A11 * DT;

    float T00 = 1.f, T01 = 0.f, T10 = 0.f, T11 = 1.f;
    float E00 = 1.f, E01 = 0.f, E10 = 0.f, E11 = 1.f;
    float P01 = 0.f, P11 = 1.f;
    #pragma unroll
    for (int k = 1; k <= 8; k++) {
        const float r   = 1.0f / (float)k;
        const float n00 = (T01 * a10) * r;
        const float n01 = (T00 * a01 + T01 * a11) * r;
        const float n10 = (T11 * a10) * r;
        const float n11 = (T10 * a01 + T11 * a11) * r;
        T00 = n00; T01 = n01; T10 = n10; T11 = n11;
        E00 += T00; E01 += T01; E10 += T10; E11 += T11;
        const float r2 = 1.0f / (float)(k + 1);
        P01 = fmaf(T01, r2, P01);
        P11 = fmaf(T11, r2, P11);
    }
    const float cx = B10 * DT;
    float2 o;
    o.x = E00 * ss0 + E01 * ss1 + P01 * cx;
    o.y = E10 * ss0 + E11 * ss1 + P11 * cx;
    return o;
}

__global__ void __launch_bounds__(THREADS, 4) joint_mma_kernel(
    const float* __restrict__ SS, const float* __restrict__ Alphas,
    const float* __restrict__ K0s, const float* __restrict__ K1s,
    const float* __restrict__ L0s, const float* __restrict__ L1s,
    const float* __restrict__ Ms,  const float* __restrict__ I_p,
    const float* __restrict__ B_p, const float* __restrict__ K_p,
    const float* __restrict__ W1, const float* __restrict__ b1g,
    const float* __restrict__ W2, const float* __restrict__ b2g,
    const float* __restrict__ W3, const float* __restrict__ b3g,
    const float* __restrict__ W4, const float* __restrict__ b4g,
    float* __restrict__ out, int B)
{
    __shared__ Smem sm;
    const int tid = threadIdx.x;

    // ---- Stage weights (transposed, bf16) + biases (f32) ----
    // Fold Ms[m] into W1 rows k=0,1 (l = ss0*Ms, dl = ss1*Ms): exact for Ms=+-1
    for (int idx = tid; idx < 1024; idx += THREADS) {   // wt1: m,o,k16
        const int k = idx & 15, o = (idx >> 4) & 31, m = idx >> 9;
        float v = 0.0f;
        if (k < 3) {
            v = W1[m * 96 + k * 32 + o];
            if (k < 2) v *= __ldg(Ms + m);
        }
        sm.wt1[m][o][k] = __float2bfloat16(v);
    }
    for (int idx = tid; idx < 2048; idx += THREADS) {   // wt2/wt3
        const int o = idx & 31, i = (idx >> 5) & 31, m = idx >> 10;
        sm.wt2[m][o][i] = __float2bfloat16(W2[idx]);
        sm.wt3[m][o][i] = __float2bfloat16(W3[idx]);
    }
    for (int idx = tid; idx < 64; idx += THREADS) {
        const int m = idx >> 5, o = idx & 31;
        sm.b1[m][o] = b1g[idx];
        sm.b2[m][o] = b2g[idx];
        sm.b3[m][o] = b3g[idx];
        sm.w4[m][o] = W4[idx];
    }
    if (tid < 2) sm.b4[tid] = b4g[tid];
    __syncthreads();

    const int l  = tid & 31, w = tid >> 5;
    const int g  = l >> 2, tc = l & 3;
    const int own_row = g + 8 * tc;

    // uniform scalars
    const float I0  = __ldg(I_p), B0p = __ldg(B_p), K0p = __ldg(K_p);
    const float invI0 = 1.0f / I0;
    const float Msv[2] = {__ldg(Ms),      __ldg(Ms + 1)};
    const float k0v[2] = {__ldg(K0s),     __ldg(K0s + 1)};
    const float k1v[2] = {__ldg(K1s),     __ldg(K1s + 1)};
    const float l0v[2] = {__ldg(L0s),     __ldg(L0s + 1)};
    const float l1v[2] = {__ldg(L1s),     __ldg(L1s + 1)};

    #pragma unroll 1
    for (int p = 0; p < PASSES; p++) {
        const int ebase = (blockIdx.x * PASSES + p) * 128 + w * 32;
        const int e = ebase + own_row;
        const float2 ss = ((const float2*)SS)[e];
        const float2 al = ((const float2*)Alphas)[e];
        const float al0 = __saturatef(al.x);
        const float al1 = __saturatef(al.y);

        // pack to bf16x2 BEFORE shuffling: 8 SHFL instead of 16
        const uint32_t ssb = pkbf(ss.x, ss.y);   // (ss0, ss1)
        const uint32_t amb = pkbf(al0, al1);     // (alpha_m0, alpha_m1)
        uint32_t ssj[4], amj[4];
        #pragma unroll
        for (int j = 0; j < 4; j++) {
            const int src = (l & ~3) + j;
            ssj[j] = __shfl_sync(0xffffffffu, ssb, src);
            amj[j] = __shfl_sync(0xffffffffu, amb, src);
        }

        float Kt = 0.f, Bs = 0.f;

        #pragma unroll
        for (int m = 0; m < 2; m++) {
            const float Msm = Msv[m], k0 = k0v[m], k1 = k1v[m], l0 = l0v[m], l1 = l1v[m];

            // ---- Layer 1 A-fragments: X rows = [ss0, ss1, alpha_m, 0...] ----
            // (Ms folded into weights; tc==0 -> (ss0,ss1), tc==1 -> (alpha_m, 0))
            uint32_t A1f[2][2];
            #pragma unroll
            for (int mt = 0; mt < 2; mt++) {
                #pragma unroll
                for (int jj = 0; jj < 2; jj++) {
                    const int j = 2 * mt + jj;
                    uint32_t v = 0u;
                    if (tc == 0)      v = ssj[j];
                    else if (tc == 1) v = m ? (amj[j] >> 16) : (amj[j] & 0xFFFFu);
                    A1f[mt][jj] = v;
                }
            }

            float d[2][4][4];

            // ---- Layer 1 mma: K=16 (one ktile), bias as C ----
            #pragma unroll
            for (int nt = 0; nt < 4; nt++) {
                const int n = nt * 8 + g;
                const float2 bias = *(const float2*)&sm.b1[m][nt * 8 + 2 * tc];
                const uint32_t b0  = *(const uint32_t*)&sm.wt1[m][n][2 * tc];
                const uint32_t b1f = *(const uint32_t*)&sm.wt1[m][n][2 * tc + 8];
                #pragma unroll
                for (int mt = 0; mt < 2; mt++)
                    mma16816(d[mt][nt], A1f[mt][0], A1f[mt][1], 0u, 0u,
                             b0, b1f, bias.x, bias.y, bias.x, bias.y);
            }

            // ---- Layers 2 and 3 ----
            #pragma unroll
            for (int L = 0; L < 2; L++) {
                // packed-bf16 leaky + repack: D(m16n8) layout == A(m16k16) layout
                uint32_t A2[2][2][4];   // [mt][kt][4]
                #pragma unroll
                for (int mt = 0; mt < 2; mt++) {
                    #pragma unroll
                    for (int kt = 0; kt < 2; kt++) {
                        const int na = 2 * kt, nb = 2 * kt + 1;
                        A2[mt][kt][0] = lkpk(d[mt][na][0], d[mt][na][1]);
                        A2[mt][kt][1] = lkpk(d[mt][na][2], d[mt][na][3]);
                        A2[mt][kt][2] = lkpk(d[mt][nb][0], d[mt][nb][1]);
                        A2[mt][kt][3] = lkpk(d[mt][nb][2], d[mt][nb][3]);
                    }
                }
                const __nv_bfloat16 (*wt)[32][40] = L ? sm.wt3 : sm.wt2;
                const float (*bb)[32] = L ? sm.b3 : sm.b2;
                #pragma unroll
                for (int nt = 0; nt < 4; nt++) {
                    const int n = nt * 8 + g;
                    const float2 bias = *(const float2*)&bb[m][nt * 8 + 2 * tc];
                    const uint32_t b00 = *(const uint32_t*)&wt[m][n][2 * tc];
                    const uint32_t b01 = *(const uint32_t*)&wt[m][n][2 * tc + 8];
                    const uint32_t b10 = *(const uint32_t*)&wt[m][n][2 * tc + 16];
                    const uint32_t b11 = *(const uint32_t*)&wt[m][n][2 * tc + 24];
                    #pragma unroll
                    for (int mt = 0; mt < 2; mt++) {
                        mma16816(d[mt][nt], A2[mt][0][0], A2[mt][0][1], A2[mt][0][2], A2[mt][0][3],
                                 b00, b01, bias.x, bias.y, bias.x, bias.y);
                        mma16816(d[mt][nt], A2[mt][1][0], A2[mt][1][1], A2[mt][1][2], A2[mt][1][3],
                                 b10, b11, d[mt][nt][0], d[mt][nt][1], d[mt][nt][2], d[mt][nt][3]);
                    }
                }
            }

            // ---- Layer 4: per-lane partial dots over its 8 cols x 4 rows (f32) ----
            float p0 = 0.f, p1 = 0.f, p2 = 0.f, p3 = 0.f;
            #pragma unroll
            for (int nt = 0; nt < 4; nt++) {
                const float2 w4p = *(const float2*)&sm.w4[m][nt * 8 + 2 * tc];
                p0 = fmaf(leaky(d[0][nt][0]), w4p.x, fmaf(leaky(d[0][nt][1]), w4p.y, p0));
                p1 = fmaf(leaky(d[0][nt][2]), w4p.x, fmaf(leaky(d[0][nt][3]), w4p.y, p1));
                p2 = fmaf(leaky(d[1][nt][0]), w4p.x, fmaf(leaky(d[1][nt][1]), w4p.y, p2));
                p3 = fmaf(leaky(d[1][nt][2]), w4p.x, fmaf(leaky(d[1][nt][3]), w4p.y, p3));
            }
            // butterfly reduce within the 4-lane col group
            p0 += __shfl_xor_sync(0xffffffffu, p0, 1);
            p0 += __shfl_xor_sync(0xffffffffu, p0, 2);
            p1 += __shfl_xor_sync(0xffffffffu, p1, 1);
            p1 += __shfl_xor_sync(0xffffffffu, p1, 2);
            p2 += __shfl_xor_sync(0xffffffffu, p2, 1);
            p2 += __shfl_xor_sync(0xffffffffu, p2, 2);
            p3 += __shfl_xor_sync(0xffffffffu, p3, 1);
            p3 += __shfl_xor_sync(0xffffffffu, p3, 2);
            // own row = g + 8*tc  ->  pick p[tc]
            const float o4 = (tc & 2) ? ((tc & 1) ? p3 : p2) : ((tc & 1) ? p1 : p0);
            const float nn = tanh_fast(o4 + sm.b4[m]) * NN_RATIO;

            // ---- physics for own element (fp32) ----
            const float amv = m ? al1 : al0;
            const float lo  = ss.x * Msm;
            const float Km  = fmaf(k1, amv, k0);
            Kt = fmaf(Km, Msm * Msm, Kt);
            const float BF = Km * (l0 + l1 * amv - fabsf(lo))
                           + k1 * l1 * amv * amv * nn;
            Bs = fmaf(BF, Msm, Bs);
        }

        const float2 rr = integrate(ss.x, ss.y, Kt, Bs, invI0, I0, B0p, K0p);
        out[e] = rr.x;
        ((float2*)(out + B))[e] = rr;
    }
}

extern "C" void kernel_launch(void* const* d_in, const int* in_sizes, int n_in,
                              void* d_out, int out_size) {
    const float* SS     = (const float*)d_in[0];
    const float* Alphas = (const float*)d_in[1];
    const float* K0s    = (const float*)d_in[2];
    const float* K1s    = (const float*)d_in[3];
    const float* L0s    = (const float*)d_in[4];
    const float* L1s    = (const float*)d_in[5];
    const float* Ms     = (const float*)d_in[6];
    const float* I_p    = (const float*)d_in[7];
    const float* B_p    = (const float*)d_in[8];
    const float* K_p    = (const float*)d_in[9];
    const float* W1     = (const float*)d_in[10];
    const float* b1     = (const float*)d_in[11];
    const float* W2     = (const float*)d_in[12];
    const float* b2     = (const float*)d_in[13];
    const float* W3     = (const float*)d_in[14];
    const float* b3     = (const float*)d_in[15];
    const float* W4     = (const float*)d_in[16];
    const float* b4     = (const float*)d_in[17];
    float* out = (float*)d_out;

    const int B = in_sizes[0] / 2;
    const int grid = B / (128 * PASSES);
    joint_mma_kernel<<<grid, THREADS>>>(SS, Alphas, K0s, K1s, L0s, L1s, Ms,
                                        I_p, B_p, K_p, W1, b1, W2, b2, W3, b3,
                                        W4, b4, out, B);
}

// round 13
// speedup vs baseline: 4.7738x; 1.0702x over previous
#include <cuda_runtime.h>
#include <cuda_bf16.h>
#include <cstdint>

#define DT       0.0166667f
#define SLOPE    0.01f
#define NN_RATIO 0.5f
#define THREADS  128
#define PASSES   4

// bf16x2 constant 0.01 (0x3C24 per half)
#define SLOPE2   0x3C243C24u

struct __align__(16) Smem {
    __nv_bfloat16 wt1[2][32][20];   // W1^T padded, Ms folded into k=0,1; k>=3 zero
    __nv_bfloat16 wt2[2][32][40];   // W2^T padded: [m][o][i]
    __nv_bfloat16 wt3[2][32][40];   // W3^T padded
    uint32_t w4b[2][16];            // w4 packed bf16x2
    float b1[2][32], b2[2][32], b3[2][32], b4[2];
};

__device__ __forceinline__ float tanh_fast(float x) {
    float y; asm("tanh.approx.f32 %0, %1;" : "=f"(y) : "f"(x)); return y;
}
// pack two f32 -> bf16x2 (lo in low half)
__device__ __forceinline__ uint32_t pkbf(float lo, float hi) {
    uint32_t r; asm("cvt.rn.bf16x2.f32 %0, %1, %2;" : "=r"(r) : "f"(hi), "f"(lo)); return r;
}
// packed leaky relu on bf16x2: max(x, 0.01*x)
__device__ __forceinline__ uint32_t lk2(uint32_t x) {
    uint32_t y, r;
    asm("mul.rn.bf16x2 %0, %1, %2;" : "=r"(y) : "r"(x), "r"(SLOPE2));
    asm("max.bf16x2 %0, %1, %2;"    : "=r"(r) : "r"(x), "r"(y));
    return r;
}
__device__ __forceinline__ uint32_t lkpk(float a, float b) { return lk2(pkbf(a, b)); }

__device__ __forceinline__ void mma16816(float* d,
    uint32_t a0, uint32_t a1, uint32_t a2, uint32_t a3,
    uint32_t b0, uint32_t b1,
    float c0, float c1, float c2, float c3)
{
    asm volatile(
        "mma.sync.aligned.m16n8k16.row.col.f32.bf16.bf16.f32 "
        "{%0,%1,%2,%3},{%4,%5,%6,%7},{%8,%9},{%10,%11,%12,%13};"
        : "=f"(d[0]), "=f"(d[1]), "=f"(d[2]), "=f"(d[3])
        : "r"(a0), "r"(a1), "r"(a2), "r"(a3), "r"(b0), "r"(b1),
          "f"(c0), "f"(c1), "f"(c2), "f"(c3));
}

// SSout = e^A*SS + phi1(A)*[0, B10*DT]^T  (closed form of the 6x6 expm)
__device__ __forceinline__ float2 integrate(float ss0, float ss1, float Ktot, float Bsum,
                                            float invI0, float I0, float B0p, float K0p) {
    const float A10 = -(Ktot + K0p) * invI0;
    const float Dd  = 2.0f * sqrtf(Ktot * I0);
    const float A11 = -(Dd + B0p) * invI0;
    const float B10 = Bsum * invI0;
    const float a01 = DT, a10 = A10 * DT, a11 = A11 * DT;

    float T00 = 1.f, T01 = 0.f, T10 = 0.f, T11 = 1.f;
    float E00 = 1.f, E01 = 0.f, E10 = 0.f, E11 = 1.f;
    float P01 = 0.f, P11 = 1.f;
    #pragma unroll
    for (int k = 1; k <= 6; k++) {
        const float r   = 1.0f / (float)k;
        const float n00 = (T01 * a10) * r;
        const float n01 = (T00 * a01 + T01 * a11) * r;
        const float n10 = (T11 * a10) * r;
        const float n11 = (T10 * a01 + T11 * a11) * r;
        T00 = n00; T01 = n01; T10 = n10; T11 = n11;
        E00 += T00; E01 += T01; E10 += T10; E11 += T11;
        const float r2 = 1.0f / (float)(k + 1);
        P01 = fmaf(T01, r2, P01);
        P11 = fmaf(T11, r2, P11);
    }
    const float cx = B10 * DT;
    float2 o;
    o.x = E00 * ss0 + E01 * ss1 + P01 * cx;
    o.y = E10 * ss0 + E11 * ss1 + P11 * cx;
    return o;
}

__global__ void __launch_bounds__(THREADS, 5) joint_mma_kernel(
    const float* __restrict__ SS, const float* __restrict__ Alphas,
    const float* __restrict__ K0s, const float* __restrict__ K1s,
    const float* __restrict__ L0s, const float* __restrict__ L1s,
    const float* __restrict__ Ms,  const float* __restrict__ I_p,
    const float* __restrict__ B_p, const float* __restrict__ K_p,
    const float* __restrict__ W1, const float* __restrict__ b1g,
    const float* __restrict__ W2, const float* __restrict__ b2g,
    const float* __restrict__ W3, const float* __restrict__ b3g,
    const float* __restrict__ W4, const float* __restrict__ b4g,
    float* __restrict__ out, int B)
{
    __shared__ Smem sm;
    const int tid = threadIdx.x;

    // ---- Stage weights (transposed, bf16) + biases (f32) ----
    // Fold Ms[m] into W1 rows k=0,1 (l = ss0*Ms, dl = ss1*Ms): exact for Ms=+-1
    for (int idx = tid; idx < 1024; idx += THREADS) {   // wt1: m,o,k16
        const int k = idx & 15, o = (idx >> 4) & 31, m = idx >> 9;
        float v = 0.0f;
        if (k < 3) {
            v = W1[m * 96 + k * 32 + o];
            if (k < 2) v *= __ldg(Ms + m);
        }
        sm.wt1[m][o][k] = __float2bfloat16(v);
    }
    for (int idx = tid; idx < 2048; idx += THREADS) {   // wt2/wt3
        const int o = idx & 31, i = (idx >> 5) & 31, m = idx >> 10;
        sm.wt2[m][o][i] = __float2bfloat16(W2[idx]);
        sm.wt3[m][o][i] = __float2bfloat16(W3[idx]);
    }
    for (int idx = tid; idx < 64; idx += THREADS) {
        const int m = idx >> 5, o = idx & 31;
        sm.b1[m][o] = b1g[idx];
        sm.b2[m][o] = b2g[idx];
        sm.b3[m][o] = b3g[idx];
    }
    if (tid < 32) {   // w4 packed bf16x2
        const int m = tid >> 4, j = tid & 15;
        sm.w4b[m][j] = pkbf(W4[m * 32 + 2 * j], W4[m * 32 + 2 * j + 1]);
    }
    if (tid < 2) sm.b4[tid] = b4g[tid];
    __syncthreads();

    const int l  = tid & 31, w = tid >> 5;
    const int g  = l >> 2, tc = l & 3;
    const int own_row = g + 8 * tc;

    // uniform scalars
    const float I0  = __ldg(I_p), B0p = __ldg(B_p), K0p = __ldg(K_p);
    const float invI0 = 1.0f / I0;
    const float Msv[2] = {__ldg(Ms),      __ldg(Ms + 1)};
    const float k0v[2] = {__ldg(K0s),     __ldg(K0s + 1)};
    const float k1v[2] = {__ldg(K1s),     __ldg(K1s + 1)};
    const float l0v[2] = {__ldg(L0s),     __ldg(L0s + 1)};
    const float l1v[2] = {__ldg(L1s),     __ldg(L1s + 1)};

    // L4 B-fragments (col 0 = w4, cols 1-7 zero): only g==0 lanes hold data
    uint32_t w4f[2][4];
    #pragma unroll
    for (int m = 0; m < 2; m++) {
        w4f[m][0] = (g == 0) ? sm.w4b[m][tc]      : 0u;   // kt0 b0
        w4f[m][1] = (g == 0) ? sm.w4b[m][tc + 4]  : 0u;   // kt0 b1
        w4f[m][2] = (g == 0) ? sm.w4b[m][tc + 8]  : 0u;   // kt1 b0
        w4f[m][3] = (g == 0) ? sm.w4b[m][tc + 12] : 0u;   // kt1 b1
    }

    #pragma unroll 1
    for (int p = 0; p < PASSES; p++) {
        const int ebase = (blockIdx.x * PASSES + p) * 128 + w * 32;
        const int e = ebase + own_row;
        const float2 ss = ((const float2*)SS)[e];
        const float2 al = ((const float2*)Alphas)[e];
        const float al0 = __saturatef(al.x);
        const float al1 = __saturatef(al.y);

        // pack to bf16x2 BEFORE shuffling: 8 SHFL
        const uint32_t ssb = pkbf(ss.x, ss.y);
        const uint32_t amb = pkbf(al0, al1);
        uint32_t ssj[4], amj[4];
        #pragma unroll
        for (int j = 0; j < 4; j++) {
            const int src = (l & ~3) + j;
            ssj[j] = __shfl_sync(0xffffffffu, ssb, src);
            amj[j] = __shfl_sync(0xffffffffu, amb, src);
        }

        float Kt = 0.f, Bs = 0.f;

        #pragma unroll
        for (int m = 0; m < 2; m++) {
            const float Msm = Msv[m], k0 = k0v[m], k1 = k1v[m], l0 = l0v[m], l1 = l1v[m];

            // ---- Layer 1 A-fragments: X rows = [ss0, ss1, alpha_m, 0...] ----
            uint32_t A1f[2][2];
            #pragma unroll
            for (int mt = 0; mt < 2; mt++) {
                #pragma unroll
                for (int jj = 0; jj < 2; jj++) {
                    const int j = 2 * mt + jj;
                    uint32_t v = 0u;
                    if (tc == 0)      v = ssj[j];
                    else if (tc == 1) v = m ? (amj[j] >> 16) : (amj[j] & 0xFFFFu);
                    A1f[mt][jj] = v;
                }
            }

            float d[2][4][4];

            // ---- Layer 1 mma: K=16, bias as C ----
            #pragma unroll
            for (int nt = 0; nt < 4; nt++) {
                const int n = nt * 8 + g;
                const float2 bias = *(const float2*)&sm.b1[m][nt * 8 + 2 * tc];
                const uint32_t b0  = *(const uint32_t*)&sm.wt1[m][n][2 * tc];
                const uint32_t b1f = *(const uint32_t*)&sm.wt1[m][n][2 * tc + 8];
                #pragma unroll
                for (int mt = 0; mt < 2; mt++)
                    mma16816(d[mt][nt], A1f[mt][0], A1f[mt][1], 0u, 0u,
                             b0, b1f, bias.x, bias.y, bias.x, bias.y);
            }

            // ---- Layers 2 and 3 ----
            uint32_t A2[2][2][4];
            #pragma unroll
            for (int L = 0; L < 2; L++) {
                // packed-bf16 leaky + repack: D(m16n8) layout == A(m16k16) layout
                #pragma unroll
                for (int mt = 0; mt < 2; mt++) {
                    #pragma unroll
                    for (int kt = 0; kt < 2; kt++) {
                        const int na = 2 * kt, nb = 2 * kt + 1;
                        A2[mt][kt][0] = lkpk(d[mt][na][0], d[mt][na][1]);
                        A2[mt][kt][1] = lkpk(d[mt][na][2], d[mt][na][3]);
                        A2[mt][kt][2] = lkpk(d[mt][nb][0], d[mt][nb][1]);
                        A2[mt][kt][3] = lkpk(d[mt][nb][2], d[mt][nb][3]);
                    }
                }
                const __nv_bfloat16 (*wt)[32][40] = L ? sm.wt3 : sm.wt2;
                const float (*bb)[32] = L ? sm.b3 : sm.b2;
                #pragma unroll
                for (int nt = 0; nt < 4; nt++) {
                    const int n = nt * 8 + g;
                    const float2 bias = *(const float2*)&bb[m][nt * 8 + 2 * tc];
                    const uint32_t b00 = *(const uint32_t*)&wt[m][n][2 * tc];
                    const uint32_t b01 = *(const uint32_t*)&wt[m][n][2 * tc + 8];
                    const uint32_t b10 = *(const uint32_t*)&wt[m][n][2 * tc + 16];
                    const uint32_t b11 = *(const uint32_t*)&wt[m][n][2 * tc + 24];
                    #pragma unroll
                    for (int mt = 0; mt < 2; mt++) {
                        mma16816(d[mt][nt], A2[mt][0][0], A2[mt][0][1], A2[mt][0][2], A2[mt][0][3],
                                 b00, b01, bias.x, bias.y, bias.x, bias.y);
                        mma16816(d[mt][nt], A2[mt][1][0], A2[mt][1][1], A2[mt][1][2], A2[mt][1][3],
                                 b10, b11, d[mt][nt][0], d[mt][nt][1], d[mt][nt][2], d[mt][nt][3]);
                    }
                }
            }

            // ---- Layer 4 as mma: leaky(L3) @ w4 (N=8, col 0 live) ----
            #pragma unroll
            for (int mt = 0; mt < 2; mt++) {
                #pragma unroll
                for (int kt = 0; kt < 2; kt++) {
                    const int na = 2 * kt, nb = 2 * kt + 1;
                    A2[mt][kt][0] = lkpk(d[mt][na][0], d[mt][na][1]);
                    A2[mt][kt][1] = lkpk(d[mt][na][2], d[mt][na][3]);
                    A2[mt][kt][2] = lkpk(d[mt][nb][0], d[mt][nb][1]);
                    A2[mt][kt][3] = lkpk(d[mt][nb][2], d[mt][nb][3]);
                }
            }
            float d4[2][4];
            #pragma unroll
            for (int mt = 0; mt < 2; mt++) {
                mma16816(d4[mt], A2[mt][0][0], A2[mt][0][1], A2[mt][0][2], A2[mt][0][3],
                         w4f[m][0], w4f[m][1], 0.f, 0.f, 0.f, 0.f);
                mma16816(d4[mt], A2[mt][1][0], A2[mt][1][1], A2[mt][1][2], A2[mt][1][3],
                         w4f[m][2], w4f[m][3], d4[mt][0], d4[mt][1], d4[mt][2], d4[mt][3]);
            }
            // distribute col-0 dots: row own_row=g+8tc lives at lane g*4,
            // tile tc>>1, reg (tc&1)*2
            const int srcl = g * 4;
            const float v00 = __shfl_sync(0xffffffffu, d4[0][0], srcl);
            const float v02 = __shfl_sync(0xffffffffu, d4[0][2], srcl);
            const float v10 = __shfl_sync(0xffffffffu, d4[1][0], srcl);
            const float v12 = __shfl_sync(0xffffffffu, d4[1][2], srcl);
            const float o4 = (tc & 2) ? ((tc & 1) ? v12 : v10)
                                      : ((tc & 1) ? v02 : v00);
            const float nn = tanh_fast(o4 + sm.b4[m]) * NN_RATIO;

            // ---- physics for own element (fp32) ----
            const float amv = m ? al1 : al0;
            const float lo  = ss.x * Msm;
            const float Km  = fmaf(k1, amv, k0);
            Kt = fmaf(Km, Msm * Msm, Kt);
            const float BF = Km * (l0 + l1 * amv - fabsf(lo))
                           + k1 * l1 * amv * amv * nn;
            Bs = fmaf(BF, Msm, Bs);
        }

        const float2 rr = integrate(ss.x, ss.y, Kt, Bs, invI0, I0, B0p, K0p);
        out[e] = rr.x;
        ((float2*)(out + B))[e] = rr;
    }
}

extern "C" void kernel_launch(void* const* d_in, const int* in_sizes, int n_in,
                              void* d_out, int out_size) {
    const float* SS     = (const float*)d_in[0];
    const float* Alphas = (const float*)d_in[1];
    const float* K0s    = (const float*)d_in[2];
    const float* K1s    = (const float*)d_in[3];
    const float* L0s    = (const float*)d_in[4];
    const float* L1s    = (const float*)d_in[5];
    const float* Ms     = (const float*)d_in[6];
    const float* I_p    = (const float*)d_in[7];
    const float* B_p    = (const float*)d_in[8];
    const float* K_p    = (const float*)d_in[9];
    const float* W1     = (const float*)d_in[10];
    const float* b1     = (const float*)d_in[11];
    const float* W2     = (const float*)d_in[12];
    const float* b2     = (const float*)d_in[13];
    const float* W3     = (const float*)d_in[14];
    const float* b3     = (const float*)d_in[15];
    const float* W4     = (const float*)d_in[16];
    const float* b4     = (const float*)d_in[17];
    float* out = (float*)d_out;

    const int B = in_sizes[0] / 2;
    const int grid = B / (128 * PASSES);
    joint_mma_kernel<<<grid, THREADS>>>(SS, Alphas, K0s, K1s, L0s, L1s, Ms,
                                        I_p, B_p, K_p, W1, b1, W2, b2, W3, b3,
                                        W4, b4, out, B);
}